// round 10
// baseline (speedup 1.0000x reference)
#include <cuda_runtime.h>
#include <cuda_fp16.h>
#include <cstdint>

#define NB 256
#define NT 256
#define NC 384
#define NH 384
#define NBT (NB*NT)

__device__ __half g_X16[(size_t)NBT*NC];
__device__ __half g_Wh[3][(size_t)NH*NC];
__device__ __half g_Q[(size_t)NBT*NH];
__device__ __half g_K[(size_t)NBT*NH];
__device__ __half g_V[(size_t)NBT*NH];

#define NEG_INF (__int_as_float((int)0xff800000))

__forceinline__ __device__ unsigned h2(float a, float b){
    __half2 h = __floats2half2_rn(a, b);
    return *reinterpret_cast<unsigned*>(&h);
}
__forceinline__ __device__ void mma16(float* c, const unsigned* a, const unsigned* b){
    asm("mma.sync.aligned.m16n8k16.row.col.f32.f16.f16.f32 "
        "{%0,%1,%2,%3}, {%4,%5,%6,%7}, {%8,%9}, {%0,%1,%2,%3};"
        : "+f"(c[0]), "+f"(c[1]), "+f"(c[2]), "+f"(c[3])
        : "r"(a[0]), "r"(a[1]), "r"(a[2]), "r"(a[3]), "r"(b[0]), "r"(b[1]));
}
__forceinline__ __device__ unsigned su32(const void* p){
    return (unsigned)__cvta_generic_to_shared(p);
}
#define CPA(dst,src) asm volatile("cp.async.ca.shared.global [%0], [%1], 16;" :: "r"(dst), "l"(src) : "memory")
#define CPC()        asm volatile("cp.async.commit_group;" ::: "memory")
#define CPW(n)       asm volatile("cp.async.wait_group %0;" :: "n"(n) : "memory")
#define LDSM4(r0,r1,r2,r3,a) \
    asm volatile("ldmatrix.sync.aligned.m8n8.x4.shared.b16 {%0,%1,%2,%3}, [%4];" \
        : "=r"(r0),"=r"(r1),"=r"(r2),"=r"(r3) : "r"(a))
#define LDSM4T(r0,r1,r2,r3,a) \
    asm volatile("ldmatrix.sync.aligned.m8n8.x4.trans.shared.b16 {%0,%1,%2,%3}, [%4];" \
        : "=r"(r0),"=r"(r1),"=r"(r2),"=r"(r3) : "r"(a))

// ============================================================================
// Kernel 0: fp32 -> fp16 preconvert of x and Wq/Wk/Wv.
// ============================================================================
__global__ __launch_bounds__(256) void cvt_kernel(
    const float* __restrict__ x, const float* __restrict__ Wk,
    const float* __restrict__ Wq, const float* __restrict__ Wv)
{
    const size_t t = (size_t)blockIdx.x * 256 + threadIdx.x;
    const size_t base = t * 8;
    if (base < (size_t)NBT*NC) {
        float4 f0 = *(const float4*)(x + base);
        float4 f1 = *(const float4*)(x + base + 4);
        *(uint4*)(g_X16 + base) = make_uint4(h2(f0.x,f0.y), h2(f0.z,f0.w),
                                             h2(f1.x,f1.y), h2(f1.z,f1.w));
    }
    if (t < (size_t)3*NH*NC/8) {
        const int w = (int)t * 8;
        const int sec = w / (NH*NC);
        const int off = w - sec * (NH*NC);
        const float* W = (sec == 0) ? Wq : (sec == 1 ? Wk : Wv);
        float4 f0 = *(const float4*)(W + off);
        float4 f1 = *(const float4*)(W + off + 4);
        *(uint4*)(g_Wh[sec] + off) = make_uint4(h2(f0.x,f0.y), h2(f0.z,f0.w),
                                                h2(f1.x,f1.y), h2(f1.z,f1.w));
    }
}

// ============================================================================
// Kernel 1: QKV projection. CTA tile 256x128, warp tile 64x64 (4m x 2n warps),
// k-tile 32, 3-stage cp.async pipeline, ldmatrix.x4 fragments.
// smem/stage: A 256x40, B 128x40 halves -> 3 stages = 92160 B.
// ============================================================================
#define PROJ_SMEM ((3*(256*40) + 3*(128*40))*2)   // 92160 B
__global__ __launch_bounds__(256) void proj_kernel()
{
    extern __shared__ __align__(16) __half dsm[];
    __half* As = dsm;            // stage stride 10240 halves
    __half* Bs = dsm + 30720;    // stage stride 5120 halves

    const int z = blockIdx.z;
    const __half* Xb = g_X16 + (size_t)(blockIdx.x*256)*NC;
    const __half* Wb = g_Wh[z] + (size_t)(blockIdx.y*128)*NC;
    __half* out = (z == 0 ? g_Q : (z == 1 ? g_K : g_V));

    const int m0 = blockIdx.x * 256, n0 = blockIdx.y * 128;
    const int tid  = threadIdx.x;
    const int lane = tid & 31, wid = tid >> 5;
    const int mw = wid & 3, nw = wid >> 2;
    const int g  = lane >> 2, th = lane & 3;

    // fills: A row = tid (4x16B), B row = tid>>1 half-row (2x16B)
    const int bfr = tid >> 1, bfc = (tid & 1) * 16;
    // ldmatrix lane address components (validated layout)
    const int aro = ((lane>>3)&1)*8 + (lane&7);
    const int akw = (lane>>4)*8;
    const int bro = (lane>>4)*8 + (lane&7);
    const int bkw = ((lane>>3)&1)*8;

    float acc[4][8][4];
    #pragma unroll
    for (int i = 0; i < 4; i++)
        #pragma unroll
        for (int q = 0; q < 8; q++)
            #pragma unroll
            for (int p = 0; p < 4; p++) acc[i][q][p] = 0.f;

    auto issue = [&](int it, int st){
        if (it < 12) {
            const int k0 = it * 32;
            const __half* gA = Xb + (size_t)tid*NC + k0;
            unsigned sA = su32(As + st*10240 + tid*40);
            CPA(sA,      gA);
            CPA(sA + 16, gA + 8);
            CPA(sA + 32, gA + 16);
            CPA(sA + 48, gA + 24);
            const __half* gB = Wb + (size_t)bfr*NC + k0 + bfc;
            unsigned sB = su32(Bs + st*5120 + bfr*40 + bfc);
            CPA(sB,      gB);
            CPA(sB + 16, gB + 8);
        }
        CPC();
    };

    issue(0, 0);
    issue(1, 1);

    int rs = 0;
    for (int it = 0; it < 12; it++) {
        CPW(1);
        __syncthreads();
        int ws = rs + 2; if (ws >= 3) ws -= 3;
        issue(it + 2, ws);

        const __half* Asr = As + rs*10240;
        const __half* Bsr = Bs + rs*5120;
        #pragma unroll
        for (int ks = 0; ks < 2; ks++) {
            unsigned a[4][4];
            #pragma unroll
            for (int mt = 0; mt < 4; mt++)
                LDSM4(a[mt][0],a[mt][1],a[mt][2],a[mt][3],
                      su32(Asr + (mw*64 + mt*16 + aro)*40 + akw + ks*16));
            unsigned b[8][2];
            #pragma unroll
            for (int p = 0; p < 4; p++) {
                unsigned r0,r1,r2,r3;
                LDSM4(r0,r1,r2,r3, su32(Bsr + (nw*64 + p*16 + bro)*40 + bkw + ks*16));
                b[2*p  ][0] = r0; b[2*p  ][1] = r1;
                b[2*p+1][0] = r2; b[2*p+1][1] = r3;
            }
            #pragma unroll
            for (int mt = 0; mt < 4; mt++)
                #pragma unroll
                for (int nt = 0; nt < 8; nt++)
                    mma16(acc[mt][nt], a[mt], b[nt]);
        }
        rs = rs + 1; if (rs >= 3) rs -= 3;
    }

    #pragma unroll
    for (int mt = 0; mt < 4; mt++)
        #pragma unroll
        for (int nt = 0; nt < 8; nt++) {
            int row = m0 + mw*64 + mt*16 + g;
            int col = n0 + nw*64 + nt*8 + 2*th;
            *(unsigned*)(out + (size_t)row*NH + col)     = h2(acc[mt][nt][0], acc[mt][nt][1]);
            *(unsigned*)(out + (size_t)(row+8)*NH + col) = h2(acc[mt][nt][2], acc[mt][nt][3]);
        }
}

// ============================================================================
// Kernel 2 (unchanged from R9): fused attention.
// ============================================================================
#define FA_SMEM 107520
__global__ __launch_bounds__(256) void attn_kernel(float* __restrict__ out)
{
    extern __shared__ __align__(16) __half dsm[];
    __shared__ float redm[2][64];
    __shared__ float reds[2][64];

    const int b = blockIdx.y, bx = blockIdx.x;
    const int qt0 = bx * 64, ncols = qt0 + 64;
    const int jmax = ncols >> 4;
    const int tid  = threadIdx.x;
    const int lane = tid & 31, wid = tid >> 5;
    const int mw = wid & 3, nw = wid >> 2;
    const int g  = lane >> 2, th = lane & 3;
    const int base = nw * 128;
    int ntc = (ncols - base) / 8;
    ntc = ntc < 0 ? 0 : (ntc > 16 ? 16 : ntc);
    const int npt = ntc >> 1;

    const __half* Qm = g_Q + (size_t)b * NT * NH;
    const __half* Km = g_K + (size_t)b * NT * NH;
    const __half* Vm = g_V + (size_t)b * NT * NH;

    const int aro = ((lane>>3)&1)*8 + (lane&7);
    const int akw = (lane>>4)*8;
    const int bro = (lane>>4)*8 + (lane&7);
    const int bkw = ((lane>>3)&1)*8;
    const int tro = (lane&7) + ((lane>>3)&1)*8;
    const int tno = (lane>>4)*8;

    __half* Qs = dsm;            // 3 stages x 64*40
    __half* Ks = dsm + 7680;     // 3 stages x 256*40

    float acc[16][4];
    #pragma unroll
    for (int i = 0; i < 16; i++)
        #pragma unroll
        for (int p = 0; p < 4; p++) acc[i][p] = 0.f;

    const int frow = tid >> 2, fcol = (tid & 3) * 8;
    const int kpasses = ncols >> 6;

    auto issue = [&](int it, int st){
        if (it < 12) {
            const int k0 = it * 32;
            CPA(su32(Qs + st*2560 + frow*40 + fcol),
                Qm + (size_t)(qt0+frow)*NH + k0 + fcol);
            for (int p = 0; p < kpasses; p++) {
                int r = p*64 + frow;
                CPA(su32(Ks + st*10240 + r*40 + fcol),
                    Km + (size_t)r*NH + k0 + fcol);
            }
        }
        CPC();
    };

    issue(0, 0);
    issue(1, 1);

    int rs = 0;
    for (int it = 0; it < 12; it++) {
        CPW(1);
        __syncthreads();
        int ws = rs + 2; if (ws >= 3) ws -= 3;
        issue(it + 2, ws);

        if (npt > 0) {
            const __half* Qr = Qs + rs*2560;
            const __half* Kr = Ks + rs*10240;
            #pragma unroll
            for (int ks = 0; ks < 2; ks++) {
                unsigned a[4];
                LDSM4(a[0],a[1],a[2],a[3], su32(Qr + (mw*16 + aro)*40 + akw + ks*16));
                #pragma unroll
                for (int p = 0; p < 8; p++) {
                    if (p < npt) {
                        unsigned r0,r1,r2,r3;
                        LDSM4(r0,r1,r2,r3, su32(Kr + (base + p*16 + bro)*40 + bkw + ks*16));
                        unsigned b0[2] = {r0,r1}, b1[2] = {r2,r3};
                        mma16(acc[2*p],   a, b0);
                        mma16(acc[2*p+1], a, b1);
                    }
                }
            }
        }
        rs = rs + 1; if (rs >= 3) rs -= 3;
    }

    const float scale = 0.05103103630798288f;
    const int r0 = mw*16 + g, r1 = r0 + 8;
    const int q0 = qt0 + r0, q1 = qt0 + r1;

    float mx0 = NEG_INF, mx1 = NEG_INF;
    #pragma unroll
    for (int nt = 0; nt < 16; nt++) {
        if (nt < ntc) {
            int c = base + nt*8 + 2*th;
            float s00 = (c   <= q0) ? acc[nt][0]*scale : NEG_INF;
            float s01 = (c+1 <= q0) ? acc[nt][1]*scale : NEG_INF;
            float s10 = (c   <= q1) ? acc[nt][2]*scale : NEG_INF;
            float s11 = (c+1 <= q1) ? acc[nt][3]*scale : NEG_INF;
            acc[nt][0]=s00; acc[nt][1]=s01; acc[nt][2]=s10; acc[nt][3]=s11;
            mx0 = fmaxf(mx0, fmaxf(s00, s01));
            mx1 = fmaxf(mx1, fmaxf(s10, s11));
        }
    }
    mx0 = fmaxf(mx0, __shfl_xor_sync(0xffffffffu, mx0, 1));
    mx0 = fmaxf(mx0, __shfl_xor_sync(0xffffffffu, mx0, 2));
    mx1 = fmaxf(mx1, __shfl_xor_sync(0xffffffffu, mx1, 1));
    mx1 = fmaxf(mx1, __shfl_xor_sync(0xffffffffu, mx1, 2));
    if (th == 0) { redm[nw][r0] = mx0; redm[nw][r1] = mx1; }
    __syncthreads();

    float M0 = fmaxf(redm[0][r0], redm[1][r0]);
    float M1 = fmaxf(redm[0][r1], redm[1][r1]);

    float sm0 = 0.f, sm1 = 0.f;
    #pragma unroll
    for (int nt = 0; nt < 16; nt++) {
        if (nt < ntc) {
            float e00 = __expf(acc[nt][0] - M0);
            float e01 = __expf(acc[nt][1] - M0);
            float e10 = __expf(acc[nt][2] - M1);
            float e11 = __expf(acc[nt][3] - M1);
            acc[nt][0]=e00; acc[nt][1]=e01; acc[nt][2]=e10; acc[nt][3]=e11;
            sm0 += e00 + e01; sm1 += e10 + e11;
        }
    }
    sm0 += __shfl_xor_sync(0xffffffffu, sm0, 1);
    sm0 += __shfl_xor_sync(0xffffffffu, sm0, 2);
    sm1 += __shfl_xor_sync(0xffffffffu, sm1, 1);
    sm1 += __shfl_xor_sync(0xffffffffu, sm1, 2);
    if (th == 0) { reds[nw][r0] = sm0; reds[nw][r1] = sm1; }
    __syncthreads();

    float inv0 = 1.f / (reds[0][r0] + reds[1][r0]);
    float inv1 = 1.f / (reds[0][r1] + reds[1][r1]);

    __half* Ps = dsm;                         // 64 x 264
    #pragma unroll
    for (int nt = 0; nt < 16; nt++) {
        if (nt < ntc) {
            int c = base + nt*8 + 2*th;
            *(unsigned*)&Ps[r0*264 + c] = h2(acc[nt][0]*inv0, acc[nt][1]*inv0);
            *(unsigned*)&Ps[r1*264 + c] = h2(acc[nt][2]*inv1, acc[nt][3]*inv1);
        }
    }
    __syncthreads();

    __half* Vb = dsm + 16896;                 // 2 stages x 256*72
    const int vrow = tid >> 3, vcol = (tid & 7) * 8;
    const int vpasses = ncols >> 5;

    auto issueV = [&](int c, int st){
        if (c < 6) {
            for (int p = 0; p < vpasses; p++) {
                int r = p*32 + vrow;
                CPA(su32(Vb + st*18432 + r*72 + vcol),
                    Vm + (size_t)r*NH + c*64 + vcol);
            }
        }
        CPC();
    };

    issueV(0, 0);
    issueV(1, 1);

    for (int c = 0; c < 6; c++) {
        CPW(1);
        __syncthreads();
        const __half* Vr = Vb + (c & 1)*18432;

        float o[4][4];
        #pragma unroll
        for (int nt = 0; nt < 4; nt++)
            #pragma unroll
            for (int p = 0; p < 4; p++) o[nt][p] = 0.f;

        for (int jt = 0; jt < jmax; jt++) {
            unsigned a[4];
            LDSM4(a[0],a[1],a[2],a[3], su32(Ps + (mw*16 + aro)*264 + jt*16 + akw));
            unsigned bb[4][2];
            #pragma unroll
            for (int cg = 0; cg < 2; cg++) {
                unsigned v0,v1,v2,v3;
                LDSM4T(v0,v1,v2,v3,
                    su32(Vr + (jt*16 + tro)*72 + nw*32 + cg*16 + tno));
                bb[2*cg  ][0] = v0; bb[2*cg  ][1] = v1;
                bb[2*cg+1][0] = v2; bb[2*cg+1][1] = v3;
            }
            #pragma unroll
            for (int nt = 0; nt < 4; nt++) mma16(o[nt], a, bb[nt]);
        }

        #pragma unroll
        for (int nt = 0; nt < 4; nt++) {
            int row = qt0 + mw*16 + g;
            int col = c*64 + nw*32 + nt*8 + 2*th;
            size_t bo = (size_t)(b*NT + row) * NH + col;
            *(float2*)(out + bo)                = make_float2(o[nt][0], o[nt][1]);
            *(float2*)(out + bo + (size_t)8*NH) = make_float2(o[nt][2], o[nt][3]);
        }
        __syncthreads();
        issueV(c + 2, c & 1);
    }
}

// ============================================================================
extern "C" void kernel_launch(void* const* d_in, const int* in_sizes, int n_in,
                              void* d_out, int out_size)
{
    const float* x  = (const float*)d_in[0];
    const float* Wk = (const float*)d_in[1];
    const float* Wq = (const float*)d_in[2];
    const float* Wv = (const float*)d_in[3];
    float* out = (float*)d_out;

    cudaFuncSetAttribute(proj_kernel, cudaFuncAttributeMaxDynamicSharedMemorySize, PROJ_SMEM);
    cudaFuncSetAttribute(attn_kernel, cudaFuncAttributeMaxDynamicSharedMemorySize, FA_SMEM);

    cvt_kernel <<<((NBT*NC/8) + 255) / 256, 256>>>(x, Wk, Wq, Wv);
    proj_kernel<<<dim3(NBT/256, NH/128, 3), 256, PROJ_SMEM>>>();
    attn_kernel<<<dim3(NT/64, NB), 256, FA_SMEM>>>(out);
}

// round 11
// speedup vs baseline: 1.1189x; 1.1189x over previous
#include <cuda_runtime.h>
#include <cuda_fp16.h>
#include <cstdint>

#define NB 256
#define NT 256
#define NC 384
#define NH 384
#define NBT (NB*NT)

__device__ __half g_X16[(size_t)NBT*NC];
__device__ __half g_Wh[3][(size_t)NH*NC];
__device__ __half g_Q[(size_t)NBT*NH];
__device__ __half g_K[(size_t)NBT*NH];
__device__ __half g_V[(size_t)NBT*NH];

#define NEG_INF (__int_as_float((int)0xff800000))

__forceinline__ __device__ unsigned h2(float a, float b){
    __half2 h = __floats2half2_rn(a, b);
    return *reinterpret_cast<unsigned*>(&h);
}
__forceinline__ __device__ void mma16(float* c, const unsigned* a, const unsigned* b){
    asm("mma.sync.aligned.m16n8k16.row.col.f32.f16.f16.f32 "
        "{%0,%1,%2,%3}, {%4,%5,%6,%7}, {%8,%9}, {%0,%1,%2,%3};"
        : "+f"(c[0]), "+f"(c[1]), "+f"(c[2]), "+f"(c[3])
        : "r"(a[0]), "r"(a[1]), "r"(a[2]), "r"(a[3]), "r"(b[0]), "r"(b[1]));
}
__forceinline__ __device__ unsigned su32(const void* p){
    return (unsigned)__cvta_generic_to_shared(p);
}
#define CPA(dst,src) asm volatile("cp.async.ca.shared.global [%0], [%1], 16;" :: "r"(dst), "l"(src) : "memory")
#define CPC()        asm volatile("cp.async.commit_group;" ::: "memory")
#define CPW(n)       asm volatile("cp.async.wait_group %0;" :: "n"(n) : "memory")
#define LDSM4(r0,r1,r2,r3,a) \
    asm volatile("ldmatrix.sync.aligned.m8n8.x4.shared.b16 {%0,%1,%2,%3}, [%4];" \
        : "=r"(r0),"=r"(r1),"=r"(r2),"=r"(r3) : "r"(a))
#define LDSM4T(r0,r1,r2,r3,a) \
    asm volatile("ldmatrix.sync.aligned.m8n8.x4.trans.shared.b16 {%0,%1,%2,%3}, [%4];" \
        : "=r"(r0),"=r"(r1),"=r"(r2),"=r"(r3) : "r"(a))

// ============================================================================
// Kernel 0: fp32 -> fp16 preconvert of x and Wq/Wk/Wv.
// ============================================================================
__global__ __launch_bounds__(256) void cvt_kernel(
    const float* __restrict__ x, const float* __restrict__ Wk,
    const float* __restrict__ Wq, const float* __restrict__ Wv)
{
    const size_t t = (size_t)blockIdx.x * 256 + threadIdx.x;
    const size_t base = t * 8;
    if (base < (size_t)NBT*NC) {
        float4 f0 = *(const float4*)(x + base);
        float4 f1 = *(const float4*)(x + base + 4);
        *(uint4*)(g_X16 + base) = make_uint4(h2(f0.x,f0.y), h2(f0.z,f0.w),
                                             h2(f1.x,f1.y), h2(f1.z,f1.w));
    }
    if (t < (size_t)3*NH*NC/8) {
        const int w = (int)t * 8;
        const int sec = w / (NH*NC);
        const int off = w - sec * (NH*NC);
        const float* W = (sec == 0) ? Wq : (sec == 1 ? Wk : Wv);
        float4 f0 = *(const float4*)(W + off);
        float4 f1 = *(const float4*)(W + off + 4);
        *(uint4*)(g_Wh[sec] + off) = make_uint4(h2(f0.x,f0.y), h2(f0.z,f0.w),
                                                h2(f1.x,f1.y), h2(f1.z,f1.w));
    }
}

// ============================================================================
// Kernel 1 (R9 config — proven optimum): QKV projection.
// CTA 128x128, warp tile 32x64, k-tile 32, 3-stage cp.async + ldmatrix.
// ============================================================================
#define PROJ_SMEM (3*(128*40)*2*2)   // 61440 B
__global__ __launch_bounds__(256) void proj_kernel()
{
    extern __shared__ __align__(16) __half dsm[];
    __half* As = dsm;            // stage stride 5120 halves
    __half* Bs = dsm + 15360;

    const int z = blockIdx.z;
    const __half* Xb = g_X16 + (size_t)(blockIdx.x*128)*NC;
    const __half* Wb = g_Wh[z] + (size_t)(blockIdx.y*128)*NC;
    __half* out = (z == 0 ? g_Q : (z == 1 ? g_K : g_V));

    const int m0 = blockIdx.x * 128, n0 = blockIdx.y * 128;
    const int tid  = threadIdx.x;
    const int lane = tid & 31, wid = tid >> 5;
    const int mw = wid & 3, nw = wid >> 2;
    const int g  = lane >> 2, th = lane & 3;

    const int frow = tid >> 1, fco = (tid & 1) * 16;
    const int arow = mw*32 + ((lane>>3)&1)*8 + (lane&7);
    const int akw  = (lane>>4)*8;
    const int brow = nw*64 + (lane>>4)*8 + (lane&7);
    const int bkw  = ((lane>>3)&1)*8;

    float acc[2][8][4];
    #pragma unroll
    for (int i = 0; i < 2; i++)
        #pragma unroll
        for (int q = 0; q < 8; q++)
            #pragma unroll
            for (int p = 0; p < 4; p++) acc[i][q][p] = 0.f;

    auto issue = [&](int it, int st){
        if (it < 12) {
            const int k0 = it * 32;
            const __half* gA = Xb + (size_t)frow*NC + k0 + fco;
            const __half* gB = Wb + (size_t)frow*NC + k0 + fco;
            unsigned sA = su32(As + st*5120 + frow*40 + fco);
            unsigned sB = su32(Bs + st*5120 + frow*40 + fco);
            CPA(sA,      gA);
            CPA(sA + 16, gA + 8);
            CPA(sB,      gB);
            CPA(sB + 16, gB + 8);
        }
        CPC();
    };

    issue(0, 0);
    issue(1, 1);

    int rs = 0;
    for (int it = 0; it < 12; it++) {
        CPW(1);
        __syncthreads();
        int ws = rs + 2; if (ws >= 3) ws -= 3;
        issue(it + 2, ws);

        const __half* Asr = As + rs*5120;
        const __half* Bsr = Bs + rs*5120;
        #pragma unroll
        for (int ks = 0; ks < 2; ks++) {
            unsigned a0[4], a1[4];
            LDSM4(a0[0],a0[1],a0[2],a0[3], su32(Asr +  arow     *40 + akw + ks*16));
            LDSM4(a1[0],a1[1],a1[2],a1[3], su32(Asr + (arow+16) *40 + akw + ks*16));
            unsigned b[8][2];
            #pragma unroll
            for (int p = 0; p < 4; p++) {
                unsigned r0,r1,r2,r3;
                LDSM4(r0,r1,r2,r3, su32(Bsr + (brow + p*16)*40 + bkw + ks*16));
                b[2*p  ][0] = r0; b[2*p  ][1] = r1;
                b[2*p+1][0] = r2; b[2*p+1][1] = r3;
            }
            #pragma unroll
            for (int nt = 0; nt < 8; nt++) {
                mma16(acc[0][nt], a0, b[nt]);
                mma16(acc[1][nt], a1, b[nt]);
            }
        }
        rs = rs + 1; if (rs >= 3) rs -= 3;
    }

    #pragma unroll
    for (int mt = 0; mt < 2; mt++)
        #pragma unroll
        for (int nt = 0; nt < 8; nt++) {
            int row = m0 + mw*32 + mt*16 + g;
            int col = n0 + nw*64 + nt*8 + 2*th;
            *(unsigned*)(out + (size_t)row*NH + col)     = h2(acc[mt][nt][0], acc[mt][nt][1]);
            *(unsigned*)(out + (size_t)(row+8)*NH + col) = h2(acc[mt][nt][2], acc[mt][nt][3]);
        }
}

// ============================================================================
// Kernel 2: fused attention with BALANCED n-split:
// warp nw covers columns [nw*ncols/2, (nw+1)*ncols/2) — both n-warps always busy.
// ============================================================================
#define FA_SMEM 107520
__global__ __launch_bounds__(256) void attn_kernel(float* __restrict__ out)
{
    extern __shared__ __align__(16) __half dsm[];
    __shared__ float redm[2][64];
    __shared__ float reds[2][64];

    const int b = blockIdx.y, bx = blockIdx.x;
    const int qt0 = bx * 64, ncols = qt0 + 64;
    const int jmax = ncols >> 4;
    const int tid  = threadIdx.x;
    const int lane = tid & 31, wid = tid >> 5;
    const int mw = wid & 3, nw = wid >> 2;
    const int g  = lane >> 2, th = lane & 3;
    // balanced split: each n-warp gets ncols/2 contiguous columns
    const int base = nw * (ncols >> 1);
    const int ntc  = ncols >> 4;      // 8-col tiles per warp (4..16, always even)
    const int npt  = ntc >> 1;        // 16-col LDSM tiles per warp

    const __half* Qm = g_Q + (size_t)b * NT * NH;
    const __half* Km = g_K + (size_t)b * NT * NH;
    const __half* Vm = g_V + (size_t)b * NT * NH;

    const int aro = ((lane>>3)&1)*8 + (lane&7);
    const int akw = (lane>>4)*8;
    const int bro = (lane>>4)*8 + (lane&7);
    const int bkw = ((lane>>3)&1)*8;
    const int tro = (lane&7) + ((lane>>3)&1)*8;
    const int tno = (lane>>4)*8;

    __half* Qs = dsm;            // 3 stages x 64*40
    __half* Ks = dsm + 7680;     // 3 stages x 256*40

    float acc[16][4];
    #pragma unroll
    for (int i = 0; i < 16; i++)
        #pragma unroll
        for (int p = 0; p < 4; p++) acc[i][p] = 0.f;

    const int frow = tid >> 2, fcol = (tid & 3) * 8;
    const int kpasses = ncols >> 6;

    auto issue = [&](int it, int st){
        if (it < 12) {
            const int k0 = it * 32;
            CPA(su32(Qs + st*2560 + frow*40 + fcol),
                Qm + (size_t)(qt0+frow)*NH + k0 + fcol);
            for (int p = 0; p < kpasses; p++) {
                int r = p*64 + frow;
                CPA(su32(Ks + st*10240 + r*40 + fcol),
                    Km + (size_t)r*NH + k0 + fcol);
            }
        }
        CPC();
    };

    issue(0, 0);
    issue(1, 1);

    int rs = 0;
    for (int it = 0; it < 12; it++) {
        CPW(1);
        __syncthreads();
        int ws = rs + 2; if (ws >= 3) ws -= 3;
        issue(it + 2, ws);

        {
            const __half* Qr = Qs + rs*2560;
            const __half* Kr = Ks + rs*10240;
            #pragma unroll
            for (int ks = 0; ks < 2; ks++) {
                unsigned a[4];
                LDSM4(a[0],a[1],a[2],a[3], su32(Qr + (mw*16 + aro)*40 + akw + ks*16));
                #pragma unroll
                for (int p = 0; p < 8; p++) {
                    if (p < npt) {
                        unsigned r0,r1,r2,r3;
                        LDSM4(r0,r1,r2,r3, su32(Kr + (base + p*16 + bro)*40 + bkw + ks*16));
                        unsigned b0[2] = {r0,r1}, b1[2] = {r2,r3};
                        mma16(acc[2*p],   a, b0);
                        mma16(acc[2*p+1], a, b1);
                    }
                }
            }
        }
        rs = rs + 1; if (rs >= 3) rs -= 3;
    }

    // ---------------- softmax (fragment-resident) ----------------
    const float scale = 0.05103103630798288f;  // 384^-0.5
    const int r0 = mw*16 + g, r1 = r0 + 8;
    const int q0 = qt0 + r0, q1 = qt0 + r1;

    float mx0 = NEG_INF, mx1 = NEG_INF;
    #pragma unroll
    for (int nt = 0; nt < 16; nt++) {
        if (nt < ntc) {
            int c = base + nt*8 + 2*th;
            float s00 = (c   <= q0) ? acc[nt][0]*scale : NEG_INF;
            float s01 = (c+1 <= q0) ? acc[nt][1]*scale : NEG_INF;
            float s10 = (c   <= q1) ? acc[nt][2]*scale : NEG_INF;
            float s11 = (c+1 <= q1) ? acc[nt][3]*scale : NEG_INF;
            acc[nt][0]=s00; acc[nt][1]=s01; acc[nt][2]=s10; acc[nt][3]=s11;
            mx0 = fmaxf(mx0, fmaxf(s00, s01));
            mx1 = fmaxf(mx1, fmaxf(s10, s11));
        }
    }
    mx0 = fmaxf(mx0, __shfl_xor_sync(0xffffffffu, mx0, 1));
    mx0 = fmaxf(mx0, __shfl_xor_sync(0xffffffffu, mx0, 2));
    mx1 = fmaxf(mx1, __shfl_xor_sync(0xffffffffu, mx1, 1));
    mx1 = fmaxf(mx1, __shfl_xor_sync(0xffffffffu, mx1, 2));
    if (th == 0) { redm[nw][r0] = mx0; redm[nw][r1] = mx1; }
    __syncthreads();

    float M0 = fmaxf(redm[0][r0], redm[1][r0]);
    float M1 = fmaxf(redm[0][r1], redm[1][r1]);

    float sm0 = 0.f, sm1 = 0.f;
    #pragma unroll
    for (int nt = 0; nt < 16; nt++) {
        if (nt < ntc) {
            float e00 = __expf(acc[nt][0] - M0);
            float e01 = __expf(acc[nt][1] - M0);
            float e10 = __expf(acc[nt][2] - M1);
            float e11 = __expf(acc[nt][3] - M1);
            acc[nt][0]=e00; acc[nt][1]=e01; acc[nt][2]=e10; acc[nt][3]=e11;
            sm0 += e00 + e01; sm1 += e10 + e11;
        }
    }
    sm0 += __shfl_xor_sync(0xffffffffu, sm0, 1);
    sm0 += __shfl_xor_sync(0xffffffffu, sm0, 2);
    sm1 += __shfl_xor_sync(0xffffffffu, sm1, 1);
    sm1 += __shfl_xor_sync(0xffffffffu, sm1, 2);
    if (th == 0) { reds[nw][r0] = sm0; reds[nw][r1] = sm1; }
    __syncthreads();

    float inv0 = 1.f / (reds[0][r0] + reds[1][r0]);
    float inv1 = 1.f / (reds[0][r1] + reds[1][r1]);

    // ---------------- P -> smem ----------------
    __half* Ps = dsm;                         // 64 x 264
    #pragma unroll
    for (int nt = 0; nt < 16; nt++) {
        if (nt < ntc) {
            int c = base + nt*8 + 2*th;
            *(unsigned*)&Ps[r0*264 + c] = h2(acc[nt][0]*inv0, acc[nt][1]*inv0);
            *(unsigned*)&Ps[r1*264 + c] = h2(acc[nt][2]*inv1, acc[nt][3]*inv1);
        }
    }
    __syncthreads();

    // ---------------- phase 2: O = P @ V ----------------
    __half* Vb = dsm + 16896;                 // 2 stages x 256*72
    const int vrow = tid >> 3, vcol = (tid & 7) * 8;
    const int vpasses = ncols >> 5;

    auto issueV = [&](int c, int st){
        if (c < 6) {
            for (int p = 0; p < vpasses; p++) {
                int r = p*32 + vrow;
                CPA(su32(Vb + st*18432 + r*72 + vcol),
                    Vm + (size_t)r*NH + c*64 + vcol);
            }
        }
        CPC();
    };

    issueV(0, 0);
    issueV(1, 1);

    for (int c = 0; c < 6; c++) {
        CPW(1);
        __syncthreads();
        const __half* Vr = Vb + (c & 1)*18432;

        float o[4][4];
        #pragma unroll
        for (int nt = 0; nt < 4; nt++)
            #pragma unroll
            for (int p = 0; p < 4; p++) o[nt][p] = 0.f;

        for (int jt = 0; jt < jmax; jt++) {
            unsigned a[4];
            LDSM4(a[0],a[1],a[2],a[3], su32(Ps + (mw*16 + aro)*264 + jt*16 + akw));
            unsigned bb[4][2];
            #pragma unroll
            for (int cg = 0; cg < 2; cg++) {
                unsigned v0,v1,v2,v3;
                LDSM4T(v0,v1,v2,v3,
                    su32(Vr + (jt*16 + tro)*72 + nw*32 + cg*16 + tno));
                bb[2*cg  ][0] = v0; bb[2*cg  ][1] = v1;
                bb[2*cg+1][0] = v2; bb[2*cg+1][1] = v3;
            }
            #pragma unroll
            for (int nt = 0; nt < 4; nt++) mma16(o[nt], a, bb[nt]);
        }

        #pragma unroll
        for (int nt = 0; nt < 4; nt++) {
            int row = qt0 + mw*16 + g;
            int col = c*64 + nw*32 + nt*8 + 2*th;
            size_t bo = (size_t)(b*NT + row) * NH + col;
            *(float2*)(out + bo)                = make_float2(o[nt][0], o[nt][1]);
            *(float2*)(out + bo + (size_t)8*NH) = make_float2(o[nt][2], o[nt][3]);
        }
        __syncthreads();
        issueV(c + 2, c & 1);
    }
}

// ============================================================================
extern "C" void kernel_launch(void* const* d_in, const int* in_sizes, int n_in,
                              void* d_out, int out_size)
{
    const float* x  = (const float*)d_in[0];
    const float* Wk = (const float*)d_in[1];
    const float* Wq = (const float*)d_in[2];
    const float* Wv = (const float*)d_in[3];
    float* out = (float*)d_out;

    cudaFuncSetAttribute(proj_kernel, cudaFuncAttributeMaxDynamicSharedMemorySize, PROJ_SMEM);
    cudaFuncSetAttribute(attn_kernel, cudaFuncAttributeMaxDynamicSharedMemorySize, FA_SMEM);

    cvt_kernel <<<((NBT*NC/8) + 255) / 256, 256>>>(x, Wk, Wq, Wv);
    proj_kernel<<<dim3(NBT/128, NH/128, 3), 256, PROJ_SMEM>>>();
    attn_kernel<<<dim3(NT/64, NB), 256, FA_SMEM>>>(out);
}